// round 4
// baseline (speedup 1.0000x reference)
#include <cuda_runtime.h>
#include <cuda_bf16.h>

#define B_ 128
#define L_ 1024
#define V_ 30000
#define D_ 256
#define T_ 64

// Scratch (static device globals: allowed; no allocations anywhere)
__device__ float g_P[V_ * T_];       // embed @ W + b              (7.68 MB)
__device__ float g_EP[V_ * T_];      // exp(embed @ W + b)         (7.68 MB)
__device__ float g_logz[B_];
__device__ float g_score[B_];

// ---------------------------------------------------------------------------
// Kernel 1: P[v][j] = sum_d embed[v][d]*W[d][j] + b[j];  EP = exp(P)
// 256 threads: j4 = tid&15 (4 cols), r = tid>>4 (8 rows) => 8x4 tile/thread,
// 128 vocab rows per block.
// ---------------------------------------------------------------------------
__global__ void __launch_bounds__(256) proj_kernel(const float* __restrict__ embed,
                                                   const float* __restrict__ W,
                                                   const float* __restrict__ bias) {
    int tid = threadIdx.x;
    int j4  = tid & 15;            // columns j4*4 .. j4*4+3
    int rg  = tid >> 4;            // 8-row group
    int vbase = blockIdx.x * 128 + rg * 8;

    const float4* Wv = reinterpret_cast<const float4*>(W);   // [D_][16] float4
    const float4* Ev[8];
    #pragma unroll
    for (int r = 0; r < 8; r++) {
        int v = min(vbase + r, V_ - 1);
        Ev[r] = reinterpret_cast<const float4*>(embed + (size_t)v * D_);
    }

    float4 bb = reinterpret_cast<const float4*>(bias)[j4];
    float4 acc[8];
    #pragma unroll
    for (int r = 0; r < 8; r++) acc[r] = bb;

    for (int d4 = 0; d4 < D_ / 4; d4++) {
        float4 w0 = Wv[(d4 * 4 + 0) * 16 + j4];
        float4 w1 = Wv[(d4 * 4 + 1) * 16 + j4];
        float4 w2 = Wv[(d4 * 4 + 2) * 16 + j4];
        float4 w3 = Wv[(d4 * 4 + 3) * 16 + j4];
        float4 e[8];
        #pragma unroll
        for (int r = 0; r < 8; r++) e[r] = Ev[r][d4];
        #pragma unroll
        for (int r = 0; r < 8; r++) {
            acc[r].x = fmaf(e[r].x, w0.x, acc[r].x);
            acc[r].y = fmaf(e[r].x, w0.y, acc[r].y);
            acc[r].z = fmaf(e[r].x, w0.z, acc[r].z);
            acc[r].w = fmaf(e[r].x, w0.w, acc[r].w);
            acc[r].x = fmaf(e[r].y, w1.x, acc[r].x);
            acc[r].y = fmaf(e[r].y, w1.y, acc[r].y);
            acc[r].z = fmaf(e[r].y, w1.z, acc[r].z);
            acc[r].w = fmaf(e[r].y, w1.w, acc[r].w);
            acc[r].x = fmaf(e[r].z, w2.x, acc[r].x);
            acc[r].y = fmaf(e[r].z, w2.y, acc[r].y);
            acc[r].z = fmaf(e[r].z, w2.z, acc[r].z);
            acc[r].w = fmaf(e[r].z, w2.w, acc[r].w);
            acc[r].x = fmaf(e[r].w, w3.x, acc[r].x);
            acc[r].y = fmaf(e[r].w, w3.y, acc[r].y);
            acc[r].z = fmaf(e[r].w, w3.z, acc[r].z);
            acc[r].w = fmaf(e[r].w, w3.w, acc[r].w);
        }
    }

    float4* Pv  = reinterpret_cast<float4*>(g_P);
    float4* EPv = reinterpret_cast<float4*>(g_EP);
    #pragma unroll
    for (int r = 0; r < 8; r++) {
        int v = vbase + r;
        if (v < V_) {
            Pv[(size_t)v * 16 + j4] = acc[r];
            float4 ex;
            ex.x = __expf(acc[r].x); ex.y = __expf(acc[r].y);
            ex.z = __expf(acc[r].z); ex.w = __expf(acc[r].w);
            EPv[(size_t)v * 16 + j4] = ex;
        }
    }
}

// ---------------------------------------------------------------------------
// Kernel 2: per-row CRF forward (linear semiring, power-of-2 rescale every 8
// steps). One block per batch row, 128 threads.
//   warp w (0..3) owns columns j = w*16 .. w*16+15
//   lane = (h = lane>>4, jl = lane&15); thread accumulates i in [h*32,h*32+32)
//   halves merged with one shfl_xor(16). ONE __syncthreads per step.
// Emission factors come PRE-EXPONENTIATED from g_EP (2-step prefetch).
// ---------------------------------------------------------------------------
__global__ void __launch_bounds__(128) crf_kernel(const int* __restrict__ x,
                                                  const int* __restrict__ tags,
                                                  const float* __restrict__ trans) {
    int row  = blockIdx.x;
    int tid  = threadIdx.x;
    int w    = tid >> 5;
    int lane = tid & 31;
    int h    = lane >> 4;
    int jl   = lane & 15;
    int j    = w * 16 + jl;

    __shared__ int   stoks[L_];
    __shared__ float p[2][T_];
    __shared__ float red[4];
    __shared__ float fin[T_];

    const int* xrow = x + (size_t)row * L_;
    const int* trow = tags + (size_t)row * L_;

    for (int i = tid; i < L_; i += 128) stoks[i] = xrow[i];

    // exp(transitions) column slice in registers
    float E[32];
    #pragma unroll
    for (int i = 0; i < 32; i++)
        E[i] = __expf(trans[(h * 32 + i) * T_ + j]);
    __syncthreads();

    // ---- gold path score ----
    float sc = 0.f;
    for (int pos = tid; pos < L_; pos += 128) {
        int tg = trow[pos];
        sc += __ldg(&g_P[(size_t)stoks[pos] * T_ + tg]);
        if (pos + 1 < L_) sc += trans[tg * T_ + trow[pos + 1]];
    }
    #pragma unroll
    for (int o = 16; o; o >>= 1) sc += __shfl_down_sync(0xffffffffu, sc, o);
    if (lane == 0) red[w] = sc;
    __syncthreads();
    if (tid == 0) {
        float tot = red[0] + red[1] + red[2] + red[3];
        tot += trans[0 * T_ + trow[0]];       // START(0) -> tag0
        tot += trans[trow[L_ - 1] * T_ + 1];  // tag_last -> END(1)
        g_score[row] = tot;
    }

    // ---- init alpha0 (exp-domain); -1e4 transitions underflow to exact 0 ----
    float e0 = __ldg(&g_P[(size_t)stoks[0] * T_ + j]);
    if (h == 0) p[0][j] = __expf(trans[j] + e0);
    // pre-exponentiated emission pipeline (2-step prefetch from g_EP)
    float ee1 = __ldg(&g_EP[(size_t)stoks[1] * T_ + j]);   // exp(e_1)
    float ee2 = __ldg(&g_EP[(size_t)stoks[2] * T_ + j]);   // exp(e_2)
    float logscale = 0.f;
    __syncthreads();

    #pragma unroll 2
    for (int t = 1; t < L_; t++) {
        float een = (t + 2 < L_) ? __ldg(&g_EP[(size_t)stoks[t + 2] * T_ + j]) : 0.f;

        const float4* qc = reinterpret_cast<const float4*>(p[(t - 1) & 1]) + h * 8;
        float4 vv[8];
        #pragma unroll
        for (int k = 0; k < 8; k++) vv[k] = qc[k];

        float r = 1.f;
        if ((t & 7) == 0) {
            // power-of-2 rescale: exponent bits only, no MUFU (ALU pipe,
            // runs concurrently with the FMA chain below)
            float m = fmaxf(fmaxf(vv[0].x, vv[0].y), fmaxf(vv[0].z, vv[0].w));
            #pragma unroll
            for (int k = 1; k < 8; k++)
                m = fmaxf(m, fmaxf(fmaxf(vv[k].x, vv[k].y), fmaxf(vv[k].z, vv[k].w)));
            m = fmaxf(m, __shfl_xor_sync(0xffffffffu, m, 16));
            int eb = (__float_as_int(m) >> 23) & 0xff;        // biased exponent
            r = __int_as_float((254 - eb) << 23);             // 2^(127-eb) = ~1/m
            logscale += (float)(eb - 127) * 0.6931471805599453f;
        }

        float a0 = 0.f, a1 = 0.f, a2 = 0.f, a3 = 0.f;
        #pragma unroll
        for (int k = 0; k < 8; k++) {
            a0 = fmaf(vv[k].x, E[4 * k + 0], a0);
            a1 = fmaf(vv[k].y, E[4 * k + 1], a1);
            a2 = fmaf(vv[k].z, E[4 * k + 2], a2);
            a3 = fmaf(vv[k].w, E[4 * k + 3], a3);
        }
        float s = (a0 + a1) + (a2 + a3);
        s += __shfl_xor_sync(0xffffffffu, s, 16);   // merge i-halves

        float q = s * (r * ee1);                     // r*ee1 ready early
        if (h == 0) p[t & 1][j] = q;

        ee1 = ee2; ee2 = een;
        __syncthreads();
    }

    // ---- log partition ----
    float v = p[(L_ - 1) & 1][j] * __expf(trans[j * T_ + 1]);
    if (h == 0) fin[j] = v;
    __syncthreads();
    if (tid < 32) {
        float s2 = fin[tid] + fin[tid + 32];
        #pragma unroll
        for (int o = 16; o; o >>= 1) s2 += __shfl_down_sync(0xffffffffu, s2, o);
        if (tid == 0) g_logz[row] = __logf(s2) + logscale;
    }
}

// ---------------------------------------------------------------------------
// Kernel 3: out = sum_b (logz - score)
// ---------------------------------------------------------------------------
__global__ void __launch_bounds__(128) reduce_kernel(float* __restrict__ out) {
    int tid = threadIdx.x;
    __shared__ float r[4];
    float v = g_logz[tid] - g_score[tid];
    #pragma unroll
    for (int o = 16; o; o >>= 1) v += __shfl_down_sync(0xffffffffu, v, o);
    if ((tid & 31) == 0) r[tid >> 5] = v;
    __syncthreads();
    if (tid == 0) out[0] = r[0] + r[1] + r[2] + r[3];
}

// ---------------------------------------------------------------------------
// metadata order: x(int), tags(int), mask(f32, unused), embed(f32), W(f32),
//                 b(f32), trans(f32)  -> out: scalar f32
// ---------------------------------------------------------------------------
extern "C" void kernel_launch(void* const* d_in, const int* in_sizes, int n_in,
                              void* d_out, int out_size) {
    const int*   x     = (const int*)d_in[0];
    const int*   tags  = (const int*)d_in[1];
    const float* embed = (const float*)d_in[3];
    const float* W     = (const float*)d_in[4];
    const float* bias  = (const float*)d_in[5];
    const float* trans = (const float*)d_in[6];
    float* out = (float*)d_out;

    proj_kernel<<<(V_ + 127) / 128, 256>>>(embed, W, bias);
    crf_kernel<<<B_, 128>>>(x, tags, trans);
    reduce_kernel<<<1, 128>>>(out);
}

// round 6
// speedup vs baseline: 1.1361x; 1.1361x over previous
#include <cuda_runtime.h>
#include <cuda_bf16.h>

#define B_ 128
#define L_ 1024
#define V_ 30000
#define D_ 256
#define T_ 64

// Scratch (static device globals: allowed; no allocations anywhere)
__device__ float g_P[V_ * T_];      // embed @ W + b   (7.68 MB)
__device__ float g_logz[B_];
__device__ float g_score[B_];

// ---------------------------------------------------------------------------
// Kernel 1: P[v][j] = sum_d embed[v][d]*W[d][j] + b[j]
// (round-3 version: 4x4 tile/thread, 64 vocab rows/block — measured 57us)
// ---------------------------------------------------------------------------
__global__ void __launch_bounds__(256) proj_kernel(const float* __restrict__ embed,
                                                   const float* __restrict__ W,
                                                   const float* __restrict__ bias) {
    int tid = threadIdx.x;
    int j4  = tid & 15;           // columns j4*4 .. j4*4+3
    int r4  = tid >> 4;           // row group (4 rows each)
    int vbase = blockIdx.x * 64 + r4 * 4;

    int v0 = min(vbase + 0, V_ - 1);
    int v1 = min(vbase + 1, V_ - 1);
    int v2 = min(vbase + 2, V_ - 1);
    int v3 = min(vbase + 3, V_ - 1);

    const float4* Wv = reinterpret_cast<const float4*>(W);   // [D_][16] float4
    const float4* E0 = reinterpret_cast<const float4*>(embed + (size_t)v0 * D_);
    const float4* E1 = reinterpret_cast<const float4*>(embed + (size_t)v1 * D_);
    const float4* E2 = reinterpret_cast<const float4*>(embed + (size_t)v2 * D_);
    const float4* E3 = reinterpret_cast<const float4*>(embed + (size_t)v3 * D_);

    float4 bb = reinterpret_cast<const float4*>(bias)[j4];
    float4 a0 = bb, a1 = bb, a2 = bb, a3 = bb;

    #pragma unroll 2
    for (int d4 = 0; d4 < D_ / 4; d4++) {
        float4 w0 = Wv[(d4 * 4 + 0) * 16 + j4];
        float4 w1 = Wv[(d4 * 4 + 1) * 16 + j4];
        float4 w2 = Wv[(d4 * 4 + 2) * 16 + j4];
        float4 w3 = Wv[(d4 * 4 + 3) * 16 + j4];
        float4 e0 = E0[d4], e1 = E1[d4], e2 = E2[d4], e3 = E3[d4];

        a0.x = fmaf(e0.x, w0.x, a0.x); a0.y = fmaf(e0.x, w0.y, a0.y);
        a0.z = fmaf(e0.x, w0.z, a0.z); a0.w = fmaf(e0.x, w0.w, a0.w);
        a0.x = fmaf(e0.y, w1.x, a0.x); a0.y = fmaf(e0.y, w1.y, a0.y);
        a0.z = fmaf(e0.y, w1.z, a0.z); a0.w = fmaf(e0.y, w1.w, a0.w);
        a0.x = fmaf(e0.z, w2.x, a0.x); a0.y = fmaf(e0.z, w2.y, a0.y);
        a0.z = fmaf(e0.z, w2.z, a0.z); a0.w = fmaf(e0.z, w2.w, a0.w);
        a0.x = fmaf(e0.w, w3.x, a0.x); a0.y = fmaf(e0.w, w3.y, a0.y);
        a0.z = fmaf(e0.w, w3.z, a0.z); a0.w = fmaf(e0.w, w3.w, a0.w);

        a1.x = fmaf(e1.x, w0.x, a1.x); a1.y = fmaf(e1.x, w0.y, a1.y);
        a1.z = fmaf(e1.x, w0.z, a1.z); a1.w = fmaf(e1.x, w0.w, a1.w);
        a1.x = fmaf(e1.y, w1.x, a1.x); a1.y = fmaf(e1.y, w1.y, a1.y);
        a1.z = fmaf(e1.y, w1.z, a1.z); a1.w = fmaf(e1.y, w1.w, a1.w);
        a1.x = fmaf(e1.z, w2.x, a1.x); a1.y = fmaf(e1.z, w2.y, a1.y);
        a1.z = fmaf(e1.z, w2.z, a1.z); a1.w = fmaf(e1.z, w2.w, a1.w);
        a1.x = fmaf(e1.w, w3.x, a1.x); a1.y = fmaf(e1.w, w3.y, a1.y);
        a1.z = fmaf(e1.w, w3.z, a1.z); a1.w = fmaf(e1.w, w3.w, a1.w);

        a2.x = fmaf(e2.x, w0.x, a2.x); a2.y = fmaf(e2.x, w0.y, a2.y);
        a2.z = fmaf(e2.x, w0.z, a2.z); a2.w = fmaf(e2.x, w0.w, a2.w);
        a2.x = fmaf(e2.y, w1.x, a2.x); a2.y = fmaf(e2.y, w1.y, a2.y);
        a2.z = fmaf(e2.y, w1.z, a2.z); a2.w = fmaf(e2.y, w1.w, a2.w);
        a2.x = fmaf(e2.z, w2.x, a2.x); a2.y = fmaf(e2.z, w2.y, a2.y);
        a2.z = fmaf(e2.z, w2.z, a2.z); a2.w = fmaf(e2.z, w2.w, a2.w);
        a2.x = fmaf(e2.w, w3.x, a2.x); a2.y = fmaf(e2.w, w3.y, a2.y);
        a2.z = fmaf(e2.w, w3.z, a2.z); a2.w = fmaf(e2.w, w3.w, a2.w);

        a3.x = fmaf(e3.x, w0.x, a3.x); a3.y = fmaf(e3.x, w0.y, a3.y);
        a3.z = fmaf(e3.x, w0.z, a3.z); a3.w = fmaf(e3.x, w0.w, a3.w);
        a3.x = fmaf(e3.y, w1.x, a3.x); a3.y = fmaf(e3.y, w1.y, a3.y);
        a3.z = fmaf(e3.y, w1.z, a3.z); a3.w = fmaf(e3.y, w1.w, a3.w);
        a3.x = fmaf(e3.z, w2.x, a3.x); a3.y = fmaf(e3.z, w2.y, a3.y);
        a3.z = fmaf(e3.z, w2.z, a3.z); a3.w = fmaf(e3.z, w2.w, a3.w);
        a3.x = fmaf(e3.w, w3.x, a3.x); a3.y = fmaf(e3.w, w3.y, a3.y);
        a3.z = fmaf(e3.w, w3.z, a3.z); a3.w = fmaf(e3.w, w3.w, a3.w);
    }

    float4* Pv = reinterpret_cast<float4*>(g_P);
    if (vbase + 0 < V_) Pv[(size_t)(vbase + 0) * 16 + j4] = a0;
    if (vbase + 1 < V_) Pv[(size_t)(vbase + 1) * 16 + j4] = a1;
    if (vbase + 2 < V_) Pv[(size_t)(vbase + 2) * 16 + j4] = a2;
    if (vbase + 3 < V_) Pv[(size_t)(vbase + 3) * 16 + j4] = a3;
}

// ---------------------------------------------------------------------------
// Kernel 2: ONE WARP PER ROW. No __syncthreads on the recursion path.
// Lane owns columns j0=lane, j1=lane+32. exp(trans) held in 128 registers.
// q (64-vector) lives in registers (2/lane); mat-vec via 64 independent
// shfl broadcasts + 128 FMAs (8 accumulators). Rescale = power-of-2, ALU only.
// ---------------------------------------------------------------------------
__global__ void __launch_bounds__(32) crf_kernel(const int* __restrict__ x,
                                                 const int* __restrict__ tags,
                                                 const float* __restrict__ trans) {
    int row  = blockIdx.x;
    int lane = threadIdx.x;
    int j0 = lane, j1 = lane + 32;

    __shared__ int   stoks[L_];
    __shared__ float strans[T_ * T_];

    const int* xrow = x + (size_t)row * L_;
    const int* trow = tags + (size_t)row * L_;

    for (int i = lane; i < L_; i += 32) stoks[i] = xrow[i];
    for (int i = lane; i < T_ * T_; i += 32) strans[i] = trans[i];
    __syncwarp();

    // exp(trans) column slices in registers (fully unrolled -> regs)
    float E0lo[32], E0hi[32], E1lo[32], E1hi[32];
    #pragma unroll
    for (int i = 0; i < 32; i++) {
        E0lo[i] = __expf(strans[i * T_ + j0]);
        E0hi[i] = __expf(strans[(i + 32) * T_ + j0]);
        E1lo[i] = __expf(strans[i * T_ + j1]);
        E1hi[i] = __expf(strans[(i + 32) * T_ + j1]);
    }

    // ---- gold path score (warp-strided) ----
    float sc = 0.f;
    #pragma unroll 4
    for (int pos = lane; pos < L_; pos += 32) {
        int tg = trow[pos];
        sc += __ldg(&g_P[(size_t)stoks[pos] * T_ + tg]);
        if (pos + 1 < L_) sc += strans[tg * T_ + trow[pos + 1]];
    }
    #pragma unroll
    for (int o = 16; o; o >>= 1) sc += __shfl_xor_sync(0xffffffffu, sc, o);
    if (lane == 0) {
        sc += strans[trow[0]];                 // START(0) -> tag0
        sc += strans[trow[L_ - 1] * T_ + 1];   // tag_last -> END(1)
        g_score[row] = sc;
    }

    // ---- init alpha0 (exp-domain); -1e4 entries underflow to exact 0 ----
    float q0 = __expf(strans[j0] + g_P[(size_t)stoks[0] * T_ + j0]);
    float q1 = __expf(strans[j1] + g_P[(size_t)stoks[0] * T_ + j1]);

    // emission pipeline: eac/ebc = exp(e_t) for t=1; ran/rbn = raw e for t=2
    float eac = __expf(__ldg(&g_P[(size_t)stoks[1] * T_ + j0]));
    float ebc = __expf(__ldg(&g_P[(size_t)stoks[1] * T_ + j1]));
    float ran = __ldg(&g_P[(size_t)stoks[2] * T_ + j0]);
    float rbn = __ldg(&g_P[(size_t)stoks[2] * T_ + j1]);
    float logscale = 0.f;

    for (int t = 1; t < L_; t++) {
        // prefetch raw emissions for t+2 (covers L2 latency ~260cyc over 2 steps)
        int pf = (t + 2 < L_) ? stoks[t + 2] : stoks[L_ - 1];
        size_t tk = (size_t)pf * T_;
        float ra2 = __ldg(&g_P[tk + j0]);
        float rb2 = __ldg(&g_P[tk + j1]);

        float r = 1.f;
        if ((t & 7) == 0) {
            // power-of-2 rescale: exponent bits only, no MUFU
            float m = fmaxf(q0, q1);
            #pragma unroll
            for (int o = 16; o; o >>= 1)
                m = fmaxf(m, __shfl_xor_sync(0xffffffffu, m, o));
            int eb = (__float_as_int(m) >> 23) & 0xff;
            r = __int_as_float((254 - eb) << 23);          // ~1/m (power of 2)
            logscale += (float)(eb - 127) * 0.6931471805599453f;
        }

        float a0 = 0.f, a1 = 0.f, a2 = 0.f, a3 = 0.f;
        float b0 = 0.f, b1 = 0.f, b2 = 0.f, b3 = 0.f;
        #pragma unroll
        for (int rr = 0; rr < 32; rr += 2) {
            float vl0 = __shfl_sync(0xffffffffu, q0, rr);
            float vh0 = __shfl_sync(0xffffffffu, q1, rr);
            float vl1 = __shfl_sync(0xffffffffu, q0, rr + 1);
            float vh1 = __shfl_sync(0xffffffffu, q1, rr + 1);
            a0 = fmaf(vl0, E0lo[rr], a0);     a1 = fmaf(vh0, E0hi[rr], a1);
            b0 = fmaf(vl0, E1lo[rr], b0);     b1 = fmaf(vh0, E1hi[rr], b1);
            a2 = fmaf(vl1, E0lo[rr + 1], a2); a3 = fmaf(vh1, E0hi[rr + 1], a3);
            b2 = fmaf(vl1, E1lo[rr + 1], b2); b3 = fmaf(vh1, E1hi[rr + 1], b3);
        }
        float s0 = (a0 + a2) + (a1 + a3);
        float s1 = (b0 + b2) + (b1 + b3);

        q0 = s0 * (r * eac);
        q1 = s1 * (r * ebc);

        // rotate emission pipeline (exp off the critical path)
        eac = __expf(ran); ebc = __expf(rbn);
        ran = ra2;         rbn = rb2;
    }

    // ---- log partition ----
    float v = q0 * __expf(strans[j0 * T_ + 1]) + q1 * __expf(strans[j1 * T_ + 1]);
    #pragma unroll
    for (int o = 16; o; o >>= 1) v += __shfl_xor_sync(0xffffffffu, v, o);
    if (lane == 0) g_logz[row] = __logf(v) + logscale;
}

// ---------------------------------------------------------------------------
// Kernel 3: out = sum_b (logz - score)
// ---------------------------------------------------------------------------
__global__ void __launch_bounds__(128) reduce_kernel(float* __restrict__ out) {
    int tid = threadIdx.x;
    __shared__ float r[4];
    float v = g_logz[tid] - g_score[tid];
    #pragma unroll
    for (int o = 16; o; o >>= 1) v += __shfl_down_sync(0xffffffffu, v, o);
    if ((tid & 31) == 0) r[tid >> 5] = v;
    __syncthreads();
    if (tid == 0) out[0] = r[0] + r[1] + r[2] + r[3];
}

// ---------------------------------------------------------------------------
// metadata order: x(int), tags(int), mask(f32, unused), embed(f32), W(f32),
//                 b(f32), trans(f32)  -> out: scalar f32
// ---------------------------------------------------------------------------
extern "C" void kernel_launch(void* const* d_in, const int* in_sizes, int n_in,
                              void* d_out, int out_size) {
    const int*   x     = (const int*)d_in[0];
    const int*   tags  = (const int*)d_in[1];
    const float* embed = (const float*)d_in[3];
    const float* W     = (const float*)d_in[4];
    const float* bias  = (const float*)d_in[5];
    const float* trans = (const float*)d_in[6];
    float* out = (float*)d_out;

    proj_kernel<<<(V_ + 63) / 64, 256>>>(embed, W, bias);
    crf_kernel<<<B_, 32>>>(x, tags, trans);
    reduce_kernel<<<1, 128>>>(out);
}

// round 7
// speedup vs baseline: 1.2370x; 1.0888x over previous
#include <cuda_runtime.h>
#include <cuda_bf16.h>

#define B_ 128
#define L_ 1024
#define V_ 30000
#define D_ 256
#define T_ 64

// Scratch (static device globals: allowed; no allocations anywhere)
__device__ float g_P[V_ * T_];      // embed @ W + b   (7.68 MB)
__device__ float g_logz[B_];
__device__ float g_score[B_];

// ---------------------------------------------------------------------------
// Kernel 1: P[v][j] = sum_d embed[v][d]*W[d][j] + b[j]
// (round-3 version: 4x4 tile/thread, 64 vocab rows/block — measured 56-57us)
// ---------------------------------------------------------------------------
__global__ void __launch_bounds__(256) proj_kernel(const float* __restrict__ embed,
                                                   const float* __restrict__ W,
                                                   const float* __restrict__ bias) {
    int tid = threadIdx.x;
    int j4  = tid & 15;           // columns j4*4 .. j4*4+3
    int r4  = tid >> 4;           // row group (4 rows each)
    int vbase = blockIdx.x * 64 + r4 * 4;

    int v0 = min(vbase + 0, V_ - 1);
    int v1 = min(vbase + 1, V_ - 1);
    int v2 = min(vbase + 2, V_ - 1);
    int v3 = min(vbase + 3, V_ - 1);

    const float4* Wv = reinterpret_cast<const float4*>(W);   // [D_][16] float4
    const float4* E0 = reinterpret_cast<const float4*>(embed + (size_t)v0 * D_);
    const float4* E1 = reinterpret_cast<const float4*>(embed + (size_t)v1 * D_);
    const float4* E2 = reinterpret_cast<const float4*>(embed + (size_t)v2 * D_);
    const float4* E3 = reinterpret_cast<const float4*>(embed + (size_t)v3 * D_);

    float4 bb = reinterpret_cast<const float4*>(bias)[j4];
    float4 a0 = bb, a1 = bb, a2 = bb, a3 = bb;

    #pragma unroll 2
    for (int d4 = 0; d4 < D_ / 4; d4++) {
        float4 w0 = Wv[(d4 * 4 + 0) * 16 + j4];
        float4 w1 = Wv[(d4 * 4 + 1) * 16 + j4];
        float4 w2 = Wv[(d4 * 4 + 2) * 16 + j4];
        float4 w3 = Wv[(d4 * 4 + 3) * 16 + j4];
        float4 e0 = E0[d4], e1 = E1[d4], e2 = E2[d4], e3 = E3[d4];

        a0.x = fmaf(e0.x, w0.x, a0.x); a0.y = fmaf(e0.x, w0.y, a0.y);
        a0.z = fmaf(e0.x, w0.z, a0.z); a0.w = fmaf(e0.x, w0.w, a0.w);
        a0.x = fmaf(e0.y, w1.x, a0.x); a0.y = fmaf(e0.y, w1.y, a0.y);
        a0.z = fmaf(e0.y, w1.z, a0.z); a0.w = fmaf(e0.y, w1.w, a0.w);
        a0.x = fmaf(e0.z, w2.x, a0.x); a0.y = fmaf(e0.z, w2.y, a0.y);
        a0.z = fmaf(e0.z, w2.z, a0.z); a0.w = fmaf(e0.z, w2.w, a0.w);
        a0.x = fmaf(e0.w, w3.x, a0.x); a0.y = fmaf(e0.w, w3.y, a0.y);
        a0.z = fmaf(e0.w, w3.z, a0.z); a0.w = fmaf(e0.w, w3.w, a0.w);

        a1.x = fmaf(e1.x, w0.x, a1.x); a1.y = fmaf(e1.x, w0.y, a1.y);
        a1.z = fmaf(e1.x, w0.z, a1.z); a1.w = fmaf(e1.x, w0.w, a1.w);
        a1.x = fmaf(e1.y, w1.x, a1.x); a1.y = fmaf(e1.y, w1.y, a1.y);
        a1.z = fmaf(e1.y, w1.z, a1.z); a1.w = fmaf(e1.y, w1.w, a1.w);
        a1.x = fmaf(e1.z, w2.x, a1.x); a1.y = fmaf(e1.z, w2.y, a1.y);
        a1.z = fmaf(e1.z, w2.z, a1.z); a1.w = fmaf(e1.z, w2.w, a1.w);
        a1.x = fmaf(e1.w, w3.x, a1.x); a1.y = fmaf(e1.w, w3.y, a1.y);
        a1.z = fmaf(e1.w, w3.z, a1.z); a1.w = fmaf(e1.w, w3.w, a1.w);

        a2.x = fmaf(e2.x, w0.x, a2.x); a2.y = fmaf(e2.x, w0.y, a2.y);
        a2.z = fmaf(e2.x, w0.z, a2.z); a2.w = fmaf(e2.x, w0.w, a2.w);
        a2.x = fmaf(e2.y, w1.x, a2.x); a2.y = fmaf(e2.y, w1.y, a2.y);
        a2.z = fmaf(e2.y, w1.z, a2.z); a2.w = fmaf(e2.y, w1.w, a2.w);
        a2.x = fmaf(e2.z, w2.x, a2.x); a2.y = fmaf(e2.z, w2.y, a2.y);
        a2.z = fmaf(e2.z, w2.z, a2.z); a2.w = fmaf(e2.z, w2.w, a2.w);
        a2.x = fmaf(e2.w, w3.x, a2.x); a2.y = fmaf(e2.w, w3.y, a2.y);
        a2.z = fmaf(e2.w, w3.z, a2.z); a2.w = fmaf(e2.w, w3.w, a2.w);

        a3.x = fmaf(e3.x, w0.x, a3.x); a3.y = fmaf(e3.x, w0.y, a3.y);
        a3.z = fmaf(e3.x, w0.z, a3.z); a3.w = fmaf(e3.x, w0.w, a3.w);
        a3.x = fmaf(e3.y, w1.x, a3.x); a3.y = fmaf(e3.y, w1.y, a3.y);
        a3.z = fmaf(e3.y, w1.z, a3.z); a3.w = fmaf(e3.y, w1.w, a3.w);
        a3.x = fmaf(e3.z, w2.x, a3.x); a3.y = fmaf(e3.z, w2.y, a3.y);
        a3.z = fmaf(e3.z, w2.z, a3.z); a3.w = fmaf(e3.z, w2.w, a3.w);
        a3.x = fmaf(e3.w, w3.x, a3.x); a3.y = fmaf(e3.w, w3.y, a3.y);
        a3.z = fmaf(e3.w, w3.z, a3.z); a3.w = fmaf(e3.w, w3.w, a3.w);
    }

    float4* Pv = reinterpret_cast<float4*>(g_P);
    if (vbase + 0 < V_) Pv[(size_t)(vbase + 0) * 16 + j4] = a0;
    if (vbase + 1 < V_) Pv[(size_t)(vbase + 1) * 16 + j4] = a1;
    if (vbase + 2 < V_) Pv[(size_t)(vbase + 2) * 16 + j4] = a2;
    if (vbase + 3 < V_) Pv[(size_t)(vbase + 3) * 16 + j4] = a3;
}

// ---------------------------------------------------------------------------
// Kernel 2: COLUMN-PER-THREAD CRF. 2 rows per block, 64 threads per row.
// Thread owns column j: holds exp(trans[0..63][j]) in 64 registers, reads the
// whole q-vector via 16 broadcast LDS.128, does 64 FMAs (4 accumulators),
// writes 1 STS. NO shuffles, NO predication on the recursion path.
// Rescale (every 8 steps): each thread computes the SAME max locally from the
// q-vector it already loaded -> no communication, deterministic.
// ---------------------------------------------------------------------------
__global__ void __launch_bounds__(128) crf_kernel(const int* __restrict__ x,
                                                  const int* __restrict__ tags,
                                                  const float* __restrict__ trans) {
    int tid = threadIdx.x;
    int rl  = tid >> 6;            // row within block (0 or 1)
    int j   = tid & 63;            // owned column
    int row = blockIdx.x * 2 + rl;

    __shared__ int   stoks[2][L_];
    __shared__ float p[2][2][T_];          // [row][buffer][col]
    __shared__ float red[2][2];
    __shared__ float strans[T_ * T_];

    const int* xrow = x + (size_t)row * L_;
    const int* trow = tags + (size_t)row * L_;

    for (int i = tid; i < T_ * T_; i += 128) strans[i] = trans[i];
    for (int i = j; i < L_; i += 64) stoks[rl][i] = xrow[i];
    __syncthreads();

    // exp(trans) column slice in registers
    float E[64];
    #pragma unroll
    for (int i = 0; i < 64; i++)
        E[i] = __expf(strans[i * T_ + j]);

    // ---- gold path score (64 threads per row) ----
    float sc = 0.f;
    #pragma unroll 4
    for (int pos = j; pos < L_; pos += 64) {
        int tg = trow[pos];
        sc += __ldg(&g_P[(size_t)stoks[rl][pos] * T_ + tg]);
        if (pos + 1 < L_) sc += strans[tg * T_ + trow[pos + 1]];
    }
    #pragma unroll
    for (int o = 16; o; o >>= 1) sc += __shfl_xor_sync(0xffffffffu, sc, o);
    if ((j & 31) == 0) red[rl][j >> 5] = sc;
    __syncthreads();
    if (j == 0) {
        float tot = red[rl][0] + red[rl][1];
        tot += strans[trow[0]];                 // START(0) -> tag0
        tot += strans[trow[L_ - 1] * T_ + 1];   // tag_last -> END(1)
        g_score[row] = tot;
    }

    // ---- init alpha0 (exp-domain); -1e4 entries underflow to exact 0 ----
    p[rl][0][j] = __expf(strans[j] + __ldg(&g_P[(size_t)stoks[rl][0] * T_ + j]));
    float ee = __expf(__ldg(&g_P[(size_t)stoks[rl][1] * T_ + j]));   // exp(e_1)
    float ra = __ldg(&g_P[(size_t)stoks[rl][2] * T_ + j]);           // raw e_2
    float logscale = 0.f;
    __syncthreads();

    for (int t = 1; t < L_; t++) {
        // prefetch raw emission for t+2 (2 steps of cover > L2 latency)
        int pf = (t + 2 < L_) ? stoks[rl][t + 2] : stoks[rl][L_ - 1];
        float ra2 = __ldg(&g_P[(size_t)pf * T_ + j]);

        // broadcast-load the whole q vector (conflict-free LDS.128)
        const float4* qc = reinterpret_cast<const float4*>(p[rl][(t - 1) & 1]);
        float4 vv[16];
        #pragma unroll
        for (int k = 0; k < 16; k++) vv[k] = qc[k];

        float r = 1.f;
        if ((t & 7) == 0) {
            // local max over the (shared) q vector -> identical in all threads
            float4 m4 = vv[0];
            #pragma unroll
            for (int k = 1; k < 16; k++) {
                m4.x = fmaxf(m4.x, vv[k].x); m4.y = fmaxf(m4.y, vv[k].y);
                m4.z = fmaxf(m4.z, vv[k].z); m4.w = fmaxf(m4.w, vv[k].w);
            }
            float m = fmaxf(fmaxf(m4.x, m4.y), fmaxf(m4.z, m4.w));
            int eb = (__float_as_int(m) >> 23) & 0xff;
            r = __int_as_float((254 - eb) << 23);          // ~1/m (power of 2)
            logscale += (float)(eb - 127) * 0.6931471805599453f;
        }

        float a0 = 0.f, a1 = 0.f, a2 = 0.f, a3 = 0.f;
        #pragma unroll
        for (int k = 0; k < 16; k++) {
            a0 = fmaf(vv[k].x, E[4 * k + 0], a0);
            a1 = fmaf(vv[k].y, E[4 * k + 1], a1);
            a2 = fmaf(vv[k].z, E[4 * k + 2], a2);
            a3 = fmaf(vv[k].w, E[4 * k + 3], a3);
        }
        p[rl][t & 1][j] = ((a0 + a1) + (a2 + a3)) * (r * ee);

        ee = __expf(ra);    // exp for next step, off critical path
        ra = ra2;
        __syncthreads();
    }

    // ---- log partition ----
    float v = p[rl][(L_ - 1) & 1][j] * __expf(strans[j * T_ + 1]);
    #pragma unroll
    for (int o = 16; o; o >>= 1) v += __shfl_xor_sync(0xffffffffu, v, o);
    if ((j & 31) == 0) red[rl][j >> 5] = v;
    __syncthreads();
    if (j == 0) g_logz[row] = __logf(red[rl][0] + red[rl][1]) + logscale;
}

// ---------------------------------------------------------------------------
// Kernel 3: out = sum_b (logz - score)
// ---------------------------------------------------------------------------
__global__ void __launch_bounds__(128) reduce_kernel(float* __restrict__ out) {
    int tid = threadIdx.x;
    __shared__ float r[4];
    float v = g_logz[tid] - g_score[tid];
    #pragma unroll
    for (int o = 16; o; o >>= 1) v += __shfl_down_sync(0xffffffffu, v, o);
    if ((tid & 31) == 0) r[tid >> 5] = v;
    __syncthreads();
    if (tid == 0) out[0] = r[0] + r[1] + r[2] + r[3];
}

// ---------------------------------------------------------------------------
// metadata order: x(int), tags(int), mask(f32, unused), embed(f32), W(f32),
//                 b(f32), trans(f32)  -> out: scalar f32
// ---------------------------------------------------------------------------
extern "C" void kernel_launch(void* const* d_in, const int* in_sizes, int n_in,
                              void* d_out, int out_size) {
    const int*   x     = (const int*)d_in[0];
    const int*   tags  = (const int*)d_in[1];
    const float* embed = (const float*)d_in[3];
    const float* W     = (const float*)d_in[4];
    const float* bias  = (const float*)d_in[5];
    const float* trans = (const float*)d_in[6];
    float* out = (float*)d_out;

    proj_kernel<<<(V_ + 63) / 64, 256>>>(embed, W, bias);
    crf_kernel<<<B_ / 2, 128>>>(x, tags, trans);
    reduce_kernel<<<1, 128>>>(out);
}

// round 8
// speedup vs baseline: 1.3674x; 1.1054x over previous
#include <cuda_runtime.h>
#include <cuda_bf16.h>

#define B_ 128
#define L_ 1024
#define V_ 30000
#define D_ 256
#define T_ 64

// Scratch (static device globals: allowed; no allocations anywhere)
__device__ float g_P[V_ * T_];      // embed @ W + b   (7.68 MB)
__device__ float g_logz[B_];
__device__ float g_score[B_];

// ---------------------------------------------------------------------------
// Kernel 1: P[v][j] = sum_d embed[v][d]*W[d][j] + b[j]
// 4x4 tile/thread; 128 threads/block => 32 vocab rows/block, 938 blocks
// (more blocks/SM than round-3's 469 to hide DRAM latency).
// ---------------------------------------------------------------------------
__global__ void __launch_bounds__(128) proj_kernel(const float* __restrict__ embed,
                                                   const float* __restrict__ W,
                                                   const float* __restrict__ bias) {
    int tid = threadIdx.x;
    int j4  = tid & 15;           // columns j4*4 .. j4*4+3
    int r4  = tid >> 4;           // row group (4 rows each), 0..7
    int vbase = blockIdx.x * 32 + r4 * 4;

    int v0 = min(vbase + 0, V_ - 1);
    int v1 = min(vbase + 1, V_ - 1);
    int v2 = min(vbase + 2, V_ - 1);
    int v3 = min(vbase + 3, V_ - 1);

    const float4* Wv = reinterpret_cast<const float4*>(W);   // [D_][16] float4
    const float4* E0 = reinterpret_cast<const float4*>(embed + (size_t)v0 * D_);
    const float4* E1 = reinterpret_cast<const float4*>(embed + (size_t)v1 * D_);
    const float4* E2 = reinterpret_cast<const float4*>(embed + (size_t)v2 * D_);
    const float4* E3 = reinterpret_cast<const float4*>(embed + (size_t)v3 * D_);

    float4 bb = reinterpret_cast<const float4*>(bias)[j4];
    float4 a0 = bb, a1 = bb, a2 = bb, a3 = bb;

    #pragma unroll 2
    for (int d4 = 0; d4 < D_ / 4; d4++) {
        float4 w0 = Wv[(d4 * 4 + 0) * 16 + j4];
        float4 w1 = Wv[(d4 * 4 + 1) * 16 + j4];
        float4 w2 = Wv[(d4 * 4 + 2) * 16 + j4];
        float4 w3 = Wv[(d4 * 4 + 3) * 16 + j4];
        float4 e0 = E0[d4], e1 = E1[d4], e2 = E2[d4], e3 = E3[d4];

        a0.x = fmaf(e0.x, w0.x, a0.x); a0.y = fmaf(e0.x, w0.y, a0.y);
        a0.z = fmaf(e0.x, w0.z, a0.z); a0.w = fmaf(e0.x, w0.w, a0.w);
        a0.x = fmaf(e0.y, w1.x, a0.x); a0.y = fmaf(e0.y, w1.y, a0.y);
        a0.z = fmaf(e0.y, w1.z, a0.z); a0.w = fmaf(e0.y, w1.w, a0.w);
        a0.x = fmaf(e0.z, w2.x, a0.x); a0.y = fmaf(e0.z, w2.y, a0.y);
        a0.z = fmaf(e0.z, w2.z, a0.z); a0.w = fmaf(e0.z, w2.w, a0.w);
        a0.x = fmaf(e0.w, w3.x, a0.x); a0.y = fmaf(e0.w, w3.y, a0.y);
        a0.z = fmaf(e0.w, w3.z, a0.z); a0.w = fmaf(e0.w, w3.w, a0.w);

        a1.x = fmaf(e1.x, w0.x, a1.x); a1.y = fmaf(e1.x, w0.y, a1.y);
        a1.z = fmaf(e1.x, w0.z, a1.z); a1.w = fmaf(e1.x, w0.w, a1.w);
        a1.x = fmaf(e1.y, w1.x, a1.x); a1.y = fmaf(e1.y, w1.y, a1.y);
        a1.z = fmaf(e1.y, w1.z, a1.z); a1.w = fmaf(e1.y, w1.w, a1.w);
        a1.x = fmaf(e1.z, w2.x, a1.x); a1.y = fmaf(e1.z, w2.y, a1.y);
        a1.z = fmaf(e1.z, w2.z, a1.z); a1.w = fmaf(e1.z, w2.w, a1.w);
        a1.x = fmaf(e1.w, w3.x, a1.x); a1.y = fmaf(e1.w, w3.y, a1.y);
        a1.z = fmaf(e1.w, w3.z, a1.z); a1.w = fmaf(e1.w, w3.w, a1.w);

        a2.x = fmaf(e2.x, w0.x, a2.x); a2.y = fmaf(e2.x, w0.y, a2.y);
        a2.z = fmaf(e2.x, w0.z, a2.z); a2.w = fmaf(e2.x, w0.w, a2.w);
        a2.x = fmaf(e2.y, w1.x, a2.x); a2.y = fmaf(e2.y, w1.y, a2.y);
        a2.z = fmaf(e2.y, w1.z, a2.z); a2.w = fmaf(e2.y, w1.w, a2.w);
        a2.x = fmaf(e2.z, w2.x, a2.x); a2.y = fmaf(e2.z, w2.y, a2.y);
        a2.z = fmaf(e2.z, w2.z, a2.z); a2.w = fmaf(e2.z, w2.w, a2.w);
        a2.x = fmaf(e2.w, w3.x, a2.x); a2.y = fmaf(e2.w, w3.y, a2.y);
        a2.z = fmaf(e2.w, w3.z, a2.z); a2.w = fmaf(e2.w, w3.w, a2.w);

        a3.x = fmaf(e3.x, w0.x, a3.x); a3.y = fmaf(e3.x, w0.y, a3.y);
        a3.z = fmaf(e3.x, w0.z, a3.z); a3.w = fmaf(e3.x, w0.w, a3.w);
        a3.x = fmaf(e3.y, w1.x, a3.x); a3.y = fmaf(e3.y, w1.y, a3.y);
        a3.z = fmaf(e3.y, w1.z, a3.z); a3.w = fmaf(e3.y, w1.w, a3.w);
        a3.x = fmaf(e3.z, w2.x, a3.x); a3.y = fmaf(e3.z, w2.y, a3.y);
        a3.z = fmaf(e3.z, w2.z, a3.z); a3.w = fmaf(e3.z, w2.w, a3.w);
        a3.x = fmaf(e3.w, w3.x, a3.x); a3.y = fmaf(e3.w, w3.y, a3.y);
        a3.z = fmaf(e3.w, w3.z, a3.z); a3.w = fmaf(e3.w, w3.w, a3.w);
    }

    float4* Pv = reinterpret_cast<float4*>(g_P);
    if (vbase + 0 < V_) Pv[(size_t)(vbase + 0) * 16 + j4] = a0;
    if (vbase + 1 < V_) Pv[(size_t)(vbase + 1) * 16 + j4] = a1;
    if (vbase + 2 < V_) Pv[(size_t)(vbase + 2) * 16 + j4] = a2;
    if (vbase + 3 < V_) Pv[(size_t)(vbase + 3) * 16 + j4] = a3;
}

// ---------------------------------------------------------------------------
// Kernel 2: COLUMN-PER-THREAD CRF. ONE row per block, 64 threads (2 warps).
// Thread owns column j: exp(trans[*][j]) in 64 regs. Step: fused
// LDS.128-broadcast + FMA loop (q float4 consumed immediately -> ~90 live
// regs, no spill), 4 accumulators, 1 STS, 1 barrier over 2 warps.
// Rescale every 8 steps: separate cheap re-read of q for the max (identical
// in all threads -> no communication), power-of-2 factor, ALU only.
// ---------------------------------------------------------------------------
__global__ void __launch_bounds__(64) crf_kernel(const int* __restrict__ x,
                                                 const int* __restrict__ tags,
                                                 const float* __restrict__ trans) {
    int j   = threadIdx.x;        // owned column
    int row = blockIdx.x;

    __shared__ int   stoks[L_];
    __shared__ float p[2][T_];
    __shared__ float red[2];
    __shared__ float strans[T_ * T_];

    const int* xrow = x + (size_t)row * L_;
    const int* trow = tags + (size_t)row * L_;

    for (int i = j; i < T_ * T_; i += 64) strans[i] = trans[i];
    for (int i = j; i < L_; i += 64) stoks[i] = xrow[i];
    __syncthreads();

    // exp(trans) column slice in registers
    float E[64];
    #pragma unroll
    for (int i = 0; i < 64; i++)
        E[i] = __expf(strans[i * T_ + j]);

    // ---- gold path score ----
    float sc = 0.f;
    #pragma unroll 4
    for (int pos = j; pos < L_; pos += 64) {
        int tg = trow[pos];
        sc += __ldg(&g_P[(size_t)stoks[pos] * T_ + tg]);
        if (pos + 1 < L_) sc += strans[tg * T_ + trow[pos + 1]];
    }
    #pragma unroll
    for (int o = 16; o; o >>= 1) sc += __shfl_xor_sync(0xffffffffu, sc, o);
    if ((j & 31) == 0) red[j >> 5] = sc;
    __syncthreads();
    if (j == 0) {
        float tot = red[0] + red[1];
        tot += strans[trow[0]];                 // START(0) -> tag0
        tot += strans[trow[L_ - 1] * T_ + 1];   // tag_last -> END(1)
        g_score[row] = tot;
    }

    // ---- init alpha0 (exp-domain); -1e4 entries underflow to exact 0 ----
    p[0][j] = __expf(strans[j] + __ldg(&g_P[(size_t)stoks[0] * T_ + j]));
    float ee = __expf(__ldg(&g_P[(size_t)stoks[1] * T_ + j]));   // exp(e_1)
    float ra = __ldg(&g_P[(size_t)stoks[2] * T_ + j]);           // raw e_2
    float logscale = 0.f;
    __syncthreads();

    for (int t = 1; t < L_; t++) {
        // prefetch raw emission for t+2
        int pf = (t + 2 < L_) ? stoks[t + 2] : stoks[L_ - 1];
        float ra2 = __ldg(&g_P[(size_t)pf * T_ + j]);

        const float4* qc = reinterpret_cast<const float4*>(p[(t - 1) & 1]);

        float r = 1.f;
        if ((t & 7) == 0) {
            // re-read q for the max (1-in-8 steps; identical in all threads)
            float4 m4 = qc[0];
            #pragma unroll
            for (int k = 1; k < 16; k++) {
                float4 v = qc[k];
                m4.x = fmaxf(m4.x, v.x); m4.y = fmaxf(m4.y, v.y);
                m4.z = fmaxf(m4.z, v.z); m4.w = fmaxf(m4.w, v.w);
            }
            float m = fmaxf(fmaxf(m4.x, m4.y), fmaxf(m4.z, m4.w));
            int eb = (__float_as_int(m) >> 23) & 0xff;
            r = __int_as_float((254 - eb) << 23);          // ~1/m (power of 2)
            logscale += (float)(eb - 127) * 0.6931471805599453f;
        }

        // fused broadcast-load + FMA: q float4 consumed immediately
        float a0 = 0.f, a1 = 0.f, a2 = 0.f, a3 = 0.f;
        #pragma unroll
        for (int k = 0; k < 16; k++) {
            float4 v = qc[k];
            a0 = fmaf(v.x, E[4 * k + 0], a0);
            a1 = fmaf(v.y, E[4 * k + 1], a1);
            a2 = fmaf(v.z, E[4 * k + 2], a2);
            a3 = fmaf(v.w, E[4 * k + 3], a3);
        }
        p[t & 1][j] = ((a0 + a1) + (a2 + a3)) * (r * ee);

        ee = __expf(ra);    // exp for next step, off critical path
        ra = ra2;
        __syncthreads();
    }

    // ---- log partition ----
    float v = p[(L_ - 1) & 1][j] * __expf(strans[j * T_ + 1]);
    #pragma unroll
    for (int o = 16; o; o >>= 1) v += __shfl_xor_sync(0xffffffffu, v, o);
    if ((j & 31) == 0) red[j >> 5] = v;
    __syncthreads();
    if (j == 0) g_logz[row] = __logf(red[0] + red[1]) + logscale;
}

// ---------------------------------------------------------------------------
// Kernel 3: out = sum_b (logz - score)
// ---------------------------------------------------------------------------
__global__ void __launch_bounds__(128) reduce_kernel(float* __restrict__ out) {
    int tid = threadIdx.x;
    __shared__ float r[4];
    float v = g_logz[tid] - g_score[tid];
    #pragma unroll
    for (int o = 16; o; o >>= 1) v += __shfl_down_sync(0xffffffffu, v, o);
    if ((tid & 31) == 0) r[tid >> 5] = v;
    __syncthreads();
    if (tid == 0) out[0] = r[0] + r[1] + r[2] + r[3];
}

// ---------------------------------------------------------------------------
// metadata order: x(int), tags(int), mask(f32, unused), embed(f32), W(f32),
//                 b(f32), trans(f32)  -> out: scalar f32
// ---------------------------------------------------------------------------
extern "C" void kernel_launch(void* const* d_in, const int* in_sizes, int n_in,
                              void* d_out, int out_size) {
    const int*   x     = (const int*)d_in[0];
    const int*   tags  = (const int*)d_in[1];
    const float* embed = (const float*)d_in[3];
    const float* W     = (const float*)d_in[4];
    const float* bias  = (const float*)d_in[5];
    const float* trans = (const float*)d_in[6];
    float* out = (float*)d_out;

    proj_kernel<<<(V_ + 31) / 32, 128>>>(embed, W, bias);
    crf_kernel<<<B_, 64>>>(x, tags, trans);
    reduce_kernel<<<1, 128>>>(out);
}